// round 17
// baseline (speedup 1.0000x reference)
#include <cuda_runtime.h>

#define H_IMG 512
#define W_IMG 512
#define NPLANES 96            // 32 * 3
#define TW 32
#define TH 32
#define IW 42                 // TW + 10
#define IH 42                 // TH + 10
#define SS2 44                // staged (g,r) float2 stride (even -> 16B-aligned windows)
#define MS4 33                // intermediate float4 stride (odd -> LDS.128 conflict-free)
#define NT 256
#define NBX 16
#define NBY 16
#define NTILES (NBX * NBY * NPLANES)   // 24576
#define NPERS 740             // 148 SMs x 5 resident CTAs
#define C1F 6.5025f
#define C2F 58.5225f
#define NPIX 25165824.0       // 32*3*512*512

__device__ float g_partials[NPERS];
__device__ unsigned int g_count = 0;

#define W11_INIT {0.00102838f, 0.00759871f, 0.03600077f, 0.10936070f, \
                  0.21300560f, 0.26601180f, 0.21300560f, 0.10936070f, \
                  0.03600077f, 0.00759871f, 0.00102838f}

__global__ void __launch_bounds__(NT, 5) ssim_main(const float* __restrict__ gen,
                                                   const float* __restrict__ ref,
                                                   float* __restrict__ out) {
    __shared__ __align__(16) float2 sgr[IH * SS2];  // staged (g, r), scaled
    __shared__ float4 pq[IH * MS4];    // (conv_h g, conv_h r, conv_h ss, conv_h gr)
    __shared__ float wsum[8];
    __shared__ double dsum[8];
    __shared__ bool is_last;

    const float W11[11] = W11_INIT;    // compile-time consts -> FFMA-imm

    const int tid = threadIdx.x;
    const int lane = tid & 31;
    const int wrp = tid >> 5;
    const int bid = blockIdx.x;

    // ---- hoisted per-thread invariants (constant across all tiles) ----
    // stage-1 item 0: item = tid
    const int ch0 = tid / IH;
    const int r0h = tid - ch0 * IH;
    const int c00 = ch0 << 2;
    const float4* const src0 = reinterpret_cast<const float4*>(sgr + r0h * SS2 + c00);
    float2* const dst0 = reinterpret_cast<float2*>(pq + r0h * MS4 + c00);
    // stage-1 item 1: item = tid + 256 (valid when tid < 80)
    const int it1 = tid + NT;
    const bool val1 = (it1 < IH * 8);
    const int ch1 = it1 / IH;
    const int r1h = it1 - ch1 * IH;
    const int c01 = ch1 << 2;
    const float4* const src1 = reinterpret_cast<const float4*>(sgr + r1h * SS2 + c01);
    float2* const dst1 = reinterpret_cast<float2*>(pq + r1h * MS4 + c01);
    // stage-2 base: rows wrp*4 .., column lane
    const float4* const vbase = pq + (wrp << 2) * MS4 + lane;

    float lsum = 0.f;

    // horizontal conv of one window: SRC float4* (7 LDS.128), DST float2*
#define HCONV(SRC, DST)                                                       \
    {                                                                         \
        float4 w4[7];                                                         \
        _Pragma("unroll")                                                     \
        for (int t = 0; t < 7; t++) w4[t] = (SRC)[t];                         \
        float2 w[14];                                                         \
        _Pragma("unroll")                                                     \
        for (int t = 0; t < 7; t++) {                                         \
            w[2 * t]     = make_float2(w4[t].x, w4[t].y);                     \
            w[2 * t + 1] = make_float2(w4[t].z, w4[t].w);                     \
        }                                                                     \
        {                                                                     \
            float s1[4] = {0.f, 0.f, 0.f, 0.f};                               \
            float s2[4] = {0.f, 0.f, 0.f, 0.f};                               \
            _Pragma("unroll")                                                 \
            for (int k = 0; k < 11; k++) {                                    \
                _Pragma("unroll")                                             \
                for (int j = 0; j < 4; j++) {                                 \
                    s1[j] = fmaf(W11[k], w[k + j].x, s1[j]);                  \
                    s2[j] = fmaf(W11[k], w[k + j].y, s2[j]);                  \
                }                                                             \
            }                                                                 \
            _Pragma("unroll")                                                 \
            for (int j = 0; j < 4; j++)                                       \
                (DST)[2 * j] = make_float2(s1[j], s2[j]);                     \
        }                                                                     \
        _Pragma("unroll")                                                     \
        for (int t = 0; t < 14; t++) {                                        \
            float gv = w[t].x;                                                \
            float rv = w[t].y;                                                \
            w[t] = make_float2(fmaf(gv, gv, rv * rv), gv * rv);               \
        }                                                                     \
        {                                                                     \
            float s3[4] = {0.f, 0.f, 0.f, 0.f};                               \
            float s4[4] = {0.f, 0.f, 0.f, 0.f};                               \
            _Pragma("unroll")                                                 \
            for (int k = 0; k < 11; k++) {                                    \
                _Pragma("unroll")                                             \
                for (int j = 0; j < 4; j++) {                                 \
                    s3[j] = fmaf(W11[k], w[k + j].x, s3[j]);                  \
                    s4[j] = fmaf(W11[k], w[k + j].y, s4[j]);                  \
                }                                                             \
            }                                                                 \
            _Pragma("unroll")                                                 \
            for (int j = 0; j < 4; j++)                                       \
                (DST)[2 * j + 1] = make_float2(s3[j], s4[j]);                 \
        }                                                                     \
    }

    for (int tile = bid; tile < NTILES; tile += NPERS) {
        // tile decode: all power-of-2 -> shifts
        const int bx = tile & (NBX - 1);
        const int by = (tile >> 4) & (NBY - 1);
        const int bz = tile >> 8;
        const int x0 = bx * TW;
        const int y0 = by * TH;
        const size_t pb = (size_t)bz * (size_t)(H_IMG * W_IMG);
        const float* gp = gen + pb;
        const float* rp = ref + pb;

        // ---- Stage 0: warp-per-row coalesced load, scale, pack, zero-pad ----
        const bool interior = (x0 >= 5) & (x0 + IW - 5 <= W_IMG) &
                              (y0 >= 5) & (y0 + IH - 5 <= H_IMG);
        if (interior) {
            const float* gb = gp + (long)(y0 - 5) * W_IMG + (x0 - 5);
            const float* rb = rp + (long)(y0 - 5) * W_IMG + (x0 - 5);
#pragma unroll
            for (int r = wrp; r < IH; r += 8) {
                const float* grow = gb + (long)r * W_IMG;
                const float* rrow = rb + (long)r * W_IMG;
                float2* srow = sgr + r * SS2;
                srow[lane] = make_float2(fmaf(grow[lane], 0.5f, 0.5f),
                                         fmaf(rrow[lane], 0.5f, 0.5f));
                if (lane < IW - 32)
                    srow[lane + 32] = make_float2(fmaf(grow[lane + 32], 0.5f, 0.5f),
                                                  fmaf(rrow[lane + 32], 0.5f, 0.5f));
            }
        } else {
#pragma unroll
            for (int r = wrp; r < IH; r += 8) {
                int gy = y0 + r - 5;
                bool rowok = (unsigned)gy < (unsigned)H_IMG;
                const float* grow = gp + (long)gy * W_IMG;
                const float* rrow = rp + (long)gy * W_IMG;
                float2* srow = sgr + r * SS2;
#pragma unroll
                for (int h = 0; h < 2; h++) {
                    int c = lane + h * 32;
                    if (c < IW) {
                        int gx = x0 + c - 5;
                        bool ok = rowok && ((unsigned)gx < (unsigned)W_IMG);
                        srow[c] = ok ? make_float2(fmaf(grow[gx], 0.5f, 0.5f),
                                                   fmaf(rrow[gx], 0.5f, 0.5f))
                                     : make_float2(0.f, 0.f);
                    }
                }
            }
        }
        __syncthreads();   // also orders prior tile's stage-2 reads before stage-1 writes

        // ---- Stage 1: horizontal conv, hoisted addressing ----
        HCONV(src0, dst0)
        if (val1) HCONV(src1, dst1)
        __syncthreads();

        // ---- Stage 2: streaming vertical conv (4 rows/thread, LDS.128) + SSIM ----
        {
            float am1[4] = {0.f, 0.f, 0.f, 0.f};
            float am2[4] = {0.f, 0.f, 0.f, 0.f};
            float ass[4] = {0.f, 0.f, 0.f, 0.f};
            float agr[4] = {0.f, 0.f, 0.f, 0.f};
#pragma unroll
            for (int t = 0; t < 14; t++) {
                float4 v = vbase[t * MS4];
#pragma unroll
                for (int j = 0; j < 4; j++) {
                    int k = t - j;
                    if (k >= 0 && k < 11) {
                        am1[j] = fmaf(W11[k], v.x, am1[j]);
                        am2[j] = fmaf(W11[k], v.y, am2[j]);
                        ass[j] = fmaf(W11[k], v.z, ass[j]);
                        agr[j] = fmaf(W11[k], v.w, agr[j]);
                    }
                }
            }
#pragma unroll
            for (int j = 0; j < 4; j++) {
                float o1 = am1[j], o2 = am2[j];
                float q = fmaf(o1, o1, o2 * o2);
                float p = o1 * o2;
                float num = fmaf(2.f, p, C1F) * fmaf(2.f, agr[j] - p, C2F);
                float den = (q + C1F) * (ass[j] - q + C2F);
                lsum += __fdividef(num, den);
            }
        }
    }
#undef HCONV

    // ---- Block reduction (fp32), once per persistent block ----
#pragma unroll
    for (int off = 16; off > 0; off >>= 1)
        lsum += __shfl_xor_sync(0xffffffffu, lsum, off);
    if (lane == 0) wsum[wrp] = lsum;
    __syncthreads();

    if (tid == 0) {
        float s = 0.f;
#pragma unroll
        for (int i = 0; i < 8; i++) s += wsum[i];
        g_partials[bid] = s;
        __threadfence();
        unsigned int t = atomicAdd(&g_count, 1u);
        is_last = (t == (unsigned)(NPERS - 1));
    }
    __syncthreads();

    // ---- Last block: deterministic final reduction ----
    if (is_last) {
        __threadfence();
        double acc = 0.0;
        for (int i = tid; i < NPERS; i += NT)
            acc += (double)g_partials[i];
#pragma unroll
        for (int off = 16; off > 0; off >>= 1)
            acc += __shfl_xor_sync(0xffffffffu, acc, off);
        if (lane == 0) dsum[wrp] = acc;
        __syncthreads();
        if (tid == 0) {
            double s = 0.0;
#pragma unroll
            for (int i = 0; i < 8; i++) s += dsum[i];
            out[0] = (float)(1.0 - s / NPIX);
            g_count = 0;   // self-reset -> graph-replay deterministic
        }
    }
}

extern "C" void kernel_launch(void* const* d_in, const int* in_sizes, int n_in,
                              void* d_out, int out_size) {
    const float* gen = (const float*)d_in[0];
    const float* ref = (const float*)d_in[1];
    float* out = (float*)d_out;

    ssim_main<<<NPERS, NT>>>(gen, ref, out);
}